// round 2
// baseline (speedup 1.0000x reference)
#include <cuda_runtime.h>
#include <math.h>

#define Bn 4
#define Hh 128
#define Ww 128
#define Aa 96
#define Dd 128
#define Tt 182
#define NITER 10
#define OPN 128.0f

#define HW (Hh*Ww)      // 16384
#define AD (Aa*Dd)      // 12288

// ---------------- persistent device state ----------------
__device__ float g_dualin[Bn*7*AD];    // ch0-4 dual, ch5 evalop, ch6 y
__device__ float g_primalin[Bn*6*HW];  // ch0-4 primal, ch5 evalop_adj
__device__ float g_pbar[Bn*5*HW];      // primal_bar
__device__ float g_tmp1[Bn*32*HW];
__device__ float g_tmp2[Bn*32*HW];
__device__ float g_cos[Aa], g_sin[Aa];

// ---------------- init ----------------
__global__ void init_kernel(const float* __restrict__ y) {
    int i = blockIdx.x*blockDim.x + threadIdx.x;
    int stride = gridDim.x*blockDim.x;
    const int N1 = Bn*7*AD, N2 = Bn*6*HW, N3 = Bn*5*HW;
    for (int idx = i; idx < N1; idx += stride) {
        int b = idx / (7*AD);
        int r = idx % (7*AD);
        int c = r / AD;
        int p = r % AD;
        g_dualin[idx] = (c == 6) ? y[b*AD + p] : 0.0f;
    }
    for (int idx = i; idx < N2; idx += stride) g_primalin[idx] = 0.0f;
    for (int idx = i; idx < N3; idx += stride) g_pbar[idx]     = 0.0f;
    if (i < Aa) {
        float ang = (float)((double)i * 3.14159265358979323846 / 96.0);
        g_cos[i] = (float)cos((double)ang);
        g_sin[i] = (float)sin((double)ang);
    }
}

// ---------------- radon forward: pbar ch1 -> dualin ch5 ----------------
// grid (Aa, Bn), block 128 (one thread per detector s), dynamic smem = 64KB image
extern __shared__ float s_dyn[];
__global__ __launch_bounds__(128) void radon_fwd_kernel() {
    float* simg = s_dyn;
    int a = blockIdx.x, b = blockIdx.y, tid = threadIdx.x;
    const float* img = g_pbar + (b*5 + 1)*HW;
    float4* s4 = (float4*)simg;
    const float4* i4 = (const float4*)img;
    for (int i = tid; i < HW/4; i += 128) s4[i] = i4[i];
    __syncthreads();

    float c  = g_cos[a];
    float sn = g_sin[a];
    float sv = (float)tid - 63.5f;
    float acc = 0.0f;
    #pragma unroll 2
    for (int t = 0; t < Tt; t++) {
        float tv = (float)t - 90.5f;
        float xi = sv*c  - tv*sn + 63.5f;
        float yi = sv*sn + tv*c  + 63.5f;
        float x0f = floorf(xi), y0f = floorf(yi);
        float wx = xi - x0f, wy = yi - y0f;
        int x0 = (int)x0f, y0 = (int)y0f;
        int x1 = x0 + 1, y1 = y0 + 1;
        bool vx0 = (x0 >= 0) & (x0 < Ww);
        bool vx1 = (x1 >= 0) & (x1 < Ww);
        bool vy0 = (y0 >= 0) & (y0 < Hh);
        bool vy1 = (y1 >= 0) & (y1 < Hh);
        int cx0 = min(max(x0,0),Ww-1), cx1 = min(max(x1,0),Ww-1);
        int cy0 = min(max(y0,0),Hh-1), cy1 = min(max(y1,0),Hh-1);
        float v00 = (vx0 && vy0) ? simg[cy0*Ww+cx0] : 0.0f;
        float v01 = (vx1 && vy0) ? simg[cy0*Ww+cx1] : 0.0f;
        float v10 = (vx0 && vy1) ? simg[cy1*Ww+cx0] : 0.0f;
        float v11 = (vx1 && vy1) ? simg[cy1*Ww+cx1] : 0.0f;
        acc += v00*(1.0f-wy)*(1.0f-wx) + v01*(1.0f-wy)*wx
             + v10*wy*(1.0f-wx)        + v11*wy*wx;
    }
    g_dualin[(b*7 + 5)*AD + a*Dd + tid] = acc * (1.0f/OPN);
}

// ---------------- radon adjoint: dualin ch0 -> primalin ch5 ----------------
// grid (32, Bn), block 256, 2 pixels/thread, dynamic smem = 48KB sinogram
__global__ __launch_bounds__(256) void radon_adj_kernel() {
    float* ssino = s_dyn;
    int b = blockIdx.y, tid = threadIdx.x;
    const float* sino = g_dualin + (b*7 + 0)*AD;
    float4* s4 = (float4*)ssino;
    const float4* i4 = (const float4*)sino;
    for (int i = tid; i < AD/4; i += 256) s4[i] = i4[i];
    __syncthreads();

    #pragma unroll
    for (int pp = 0; pp < 2; pp++) {
        int p = (blockIdx.x*2 + pp)*256 + tid;
        int yy = p >> 7, xx = p & 127;
        float px = (float)xx - 63.5f;
        float py = (float)yy - 63.5f;
        float acc = 0.0f;
        for (int a = 0; a < Aa; a++) {
            float det = px*g_cos[a] + py*g_sin[a] + 63.5f;
            float d0f = floorf(det);
            float w = det - d0f;
            int d0 = (int)d0f;
            int d1 = d0 + 1;
            float v0 = (d0 >= 0 && d0 < Dd) ? ssino[a*Dd + d0] : 0.0f;
            float v1 = (d1 >= 0 && d1 < Dd) ? ssino[a*Dd + d1] : 0.0f;
            acc += v0*(1.0f-w) + v1*w;
        }
        g_primalin[(b*6 + 5)*HW + p] = acc * (1.0f/OPN);
    }
}

// ---------------- generic conv3x3 + relu ----------------
// in: planar [B][CIN][HH][WW] with batch stride CIN*HH*WW; WW must be 128.
template<int CIN, int COUT, int HH>
__global__ __launch_bounds__(256) void conv_relu_kernel(
    const float* __restrict__ in, const float* __restrict__ w,
    const float* __restrict__ bias, float* __restrict__ out)
{
    __shared__ float sw[9*CIN*COUT];
    __shared__ float sb[COUT];
    const int NPIX = HH*128;
    int tid = threadIdx.x;
    for (int i = tid; i < 9*CIN*COUT; i += 256) sw[i] = w[i];
    if (tid < COUT) sb[tid] = bias[tid];
    __syncthreads();

    int b = blockIdx.y;
    int p = blockIdx.x*256 + tid;
    int y = p >> 7, x = p & 127;
    const float* inb = in + b*CIN*NPIX;

    float acc[COUT];
    #pragma unroll
    for (int co = 0; co < COUT; co++) acc[co] = sb[co];

    #pragma unroll
    for (int ky = 0; ky < 3; ky++) {
        int iy = y + ky - 1;
        if (iy < 0 || iy >= HH) continue;
        #pragma unroll
        for (int kx = 0; kx < 3; kx++) {
            int ix = x + kx - 1;
            if (ix < 0 || ix >= 128) continue;
            const float* ip = inb + iy*128 + ix;
            const float* wp = sw + (ky*3 + kx)*CIN*COUT;
            for (int ci = 0; ci < CIN; ci++) {
                float v = __ldg(ip + ci*NPIX);
                const float4* wr = (const float4*)(wp + ci*COUT);
                #pragma unroll
                for (int q = 0; q < COUT/4; q++) {
                    float4 wv = wr[q];
                    acc[4*q+0] += v*wv.x;
                    acc[4*q+1] += v*wv.y;
                    acc[4*q+2] += v*wv.z;
                    acc[4*q+3] += v*wv.w;
                }
            }
        }
    }
    float* ob = out + b*COUT*NPIX;
    #pragma unroll
    for (int co = 0; co < COUT; co++) ob[co*NPIX + p] = fmaxf(acc[co], 0.0f);
}

// ---------------- conv3x3 (32->5) + dual update ----------------
__global__ __launch_bounds__(256) void conv_dual_update_kernel(
    const float* __restrict__ in, const float* __restrict__ w,
    const float* __restrict__ bias, const float* __restrict__ sigma)
{
    __shared__ float sw[9*32*5];
    __shared__ float sb[5];
    int tid = threadIdx.x;
    for (int i = tid; i < 9*32*5; i += 256) sw[i] = w[i];
    if (tid < 5) sb[tid] = bias[tid];
    __syncthreads();

    int b = blockIdx.y;
    int p = blockIdx.x*256 + tid;
    int y = p >> 7, x = p & 127;
    const float* inb = in + b*32*AD;

    float acc[5];
    #pragma unroll
    for (int co = 0; co < 5; co++) acc[co] = sb[co];

    #pragma unroll
    for (int ky = 0; ky < 3; ky++) {
        int iy = y + ky - 1;
        if (iy < 0 || iy >= Aa) continue;
        #pragma unroll
        for (int kx = 0; kx < 3; kx++) {
            int ix = x + kx - 1;
            if (ix < 0 || ix >= 128) continue;
            const float* ip = inb + iy*128 + ix;
            const float* wp = sw + (ky*3 + kx)*32*5;
            for (int ci = 0; ci < 32; ci++) {
                float v = __ldg(ip + ci*AD);
                const float* wr = wp + ci*5;
                #pragma unroll
                for (int co = 0; co < 5; co++) acc[co] += v*wr[co];
            }
        }
    }
    float sg = __ldg(sigma);
    #pragma unroll
    for (int co = 0; co < 5; co++) {
        float* dp = g_dualin + (b*7 + co)*AD + p;
        *dp = *dp + sg*acc[co];
    }
}

// ---------------- conv3x3 (32->5) + primal & pbar update ----------------
__global__ __launch_bounds__(256) void conv_primal_update_kernel(
    const float* __restrict__ in, const float* __restrict__ w,
    const float* __restrict__ bias, const float* __restrict__ tau,
    const float* __restrict__ theta)
{
    __shared__ float sw[9*32*5];
    __shared__ float sb[5];
    int tid = threadIdx.x;
    for (int i = tid; i < 9*32*5; i += 256) sw[i] = w[i];
    if (tid < 5) sb[tid] = bias[tid];
    __syncthreads();

    int b = blockIdx.y;
    int p = blockIdx.x*256 + tid;
    int y = p >> 7, x = p & 127;
    const float* inb = in + b*32*HW;

    float acc[5];
    #pragma unroll
    for (int co = 0; co < 5; co++) acc[co] = sb[co];

    #pragma unroll
    for (int ky = 0; ky < 3; ky++) {
        int iy = y + ky - 1;
        if (iy < 0 || iy >= Hh) continue;
        #pragma unroll
        for (int kx = 0; kx < 3; kx++) {
            int ix = x + kx - 1;
            if (ix < 0 || ix >= 128) continue;
            const float* ip = inb + iy*128 + ix;
            const float* wp = sw + (ky*3 + kx)*32*5;
            for (int ci = 0; ci < 32; ci++) {
                float v = __ldg(ip + ci*HW);
                const float* wr = wp + ci*5;
                #pragma unroll
                for (int co = 0; co < 5; co++) acc[co] += v*wr[co];
            }
        }
    }
    float tv = __ldg(tau);
    float th = __ldg(theta);
    #pragma unroll
    for (int co = 0; co < 5; co++) {
        float* pp = g_primalin + (b*6 + co)*HW + p;
        float oldv = *pp;
        float nv = oldv + tv*acc[co];
        *pp = nv;
        g_pbar[(b*5 + co)*HW + p] = nv + th*(nv - oldv);
    }
}

// ---------------- output ----------------
__global__ void output_kernel(float* __restrict__ out) {
    int i = blockIdx.x*blockDim.x + threadIdx.x;
    if (i < Bn*HW) {
        int b = i / HW, p = i % HW;
        out[i] = g_primalin[(b*6 + 0)*HW + p];
    }
}

// ---------------- launch ----------------
extern "C" void kernel_launch(void* const* d_in, const int* in_sizes, int n_in,
                              void* d_out, int out_size)
{
    const float* y     = (const float*)d_in[0];
    const float* sigma = (const float*)d_in[1];
    const float* tau   = (const float*)d_in[2];
    const float* theta = (const float*)d_in[3];
    const float* dw1 = (const float*)d_in[4];
    const float* db1 = (const float*)d_in[5];
    const float* dw2 = (const float*)d_in[6];
    const float* db2 = (const float*)d_in[7];
    const float* dw3 = (const float*)d_in[8];
    const float* db3 = (const float*)d_in[9];
    const float* pw1 = (const float*)d_in[10];
    const float* pb1 = (const float*)d_in[11];
    const float* pw2 = (const float*)d_in[12];
    const float* pb2 = (const float*)d_in[13];
    const float* pw3 = (const float*)d_in[14];
    const float* pb3 = (const float*)d_in[15];

    // Resolve REAL device addresses of the __device__ globals (host-side
    // symbol names are shadow addresses — passing them directly is the bug
    // that broke round 1).
    float *p_dualin, *p_primalin, *p_tmp1, *p_tmp2;
    cudaGetSymbolAddress((void**)&p_dualin,   g_dualin);
    cudaGetSymbolAddress((void**)&p_primalin, g_primalin);
    cudaGetSymbolAddress((void**)&p_tmp1,     g_tmp1);
    cudaGetSymbolAddress((void**)&p_tmp2,     g_tmp2);

    cudaFuncSetAttribute(radon_fwd_kernel, cudaFuncAttributeMaxDynamicSharedMemorySize, 65536);
    cudaFuncSetAttribute(radon_adj_kernel, cudaFuncAttributeMaxDynamicSharedMemorySize, 49152);

    init_kernel<<<512, 256>>>(y);

    for (int it = 0; it < NITER; it++) {
        // dual branch
        radon_fwd_kernel<<<dim3(Aa, Bn), 128, 65536>>>();
        conv_relu_kernel<7, 32, Aa><<<dim3(AD/256, Bn), 256>>>(p_dualin, dw1, db1, p_tmp1);
        conv_relu_kernel<32, 32, Aa><<<dim3(AD/256, Bn), 256>>>(p_tmp1, dw2, db2, p_tmp2);
        conv_dual_update_kernel<<<dim3(AD/256, Bn), 256>>>(p_tmp2, dw3, db3, sigma);
        // primal branch
        radon_adj_kernel<<<dim3(32, Bn), 256, 49152>>>();
        conv_relu_kernel<6, 32, Hh><<<dim3(HW/256, Bn), 256>>>(p_primalin, pw1, pb1, p_tmp1);
        conv_relu_kernel<32, 32, Hh><<<dim3(HW/256, Bn), 256>>>(p_tmp1, pw2, pb2, p_tmp2);
        conv_primal_update_kernel<<<dim3(HW/256, Bn), 256>>>(p_tmp2, pw3, pb3, tau, theta);
    }

    output_kernel<<<(Bn*HW + 255)/256, 256>>>((float*)d_out);
}